// round 1
// baseline (speedup 1.0000x reference)
#include <cuda_runtime.h>
#include <math.h>

#define B_    64
#define U_    512
#define CORE_ 512
#define UNIT_ 256
#define HID_  1024
#define ACT_  12
#define M_    (B_*U_)

// scratch: core_output @ W1[256:768] + b1, per batch  (64 x 1024 = 256KB)
__device__ float g_core_part[B_ * HID_];

// ---------------------------------------------------------------------------
// Kernel 1: core_part[b][h] = sum_k core[b][k] * W1[256+k][h] + b1[h]
// grid (HID/128, B), 128 threads
// ---------------------------------------------------------------------------
__global__ __launch_bounds__(128) void core_part_kernel(
    const float* __restrict__ core, const float* __restrict__ W1,
    const float* __restrict__ b1) {
    int b = blockIdx.y;
    int h = blockIdx.x * 128 + threadIdx.x;
    __shared__ float cs[CORE_];
    for (int i = threadIdx.x; i < CORE_; i += 128) cs[i] = core[b * CORE_ + i];
    __syncthreads();
    float acc = b1[h];
    const float* w = W1 + (size_t)UNIT_ * HID_ + h;
#pragma unroll 8
    for (int k = 0; k < CORE_; k++) acc += cs[k] * w[(size_t)k * HID_];
    g_core_part[b * HID_ + h] = acc;
}

// ---------------------------------------------------------------------------
// Kernel 2: out_emb[row][h] = relu( emb[row][0:256] @ W1[0:256][h] + core_part[b][h] )
// M=32768, N=1024, K=256.  Tile 128x128x16, 256 threads, 8x8 per thread.
// ---------------------------------------------------------------------------
#define TM 128
#define TN 128
#define TK 16

__global__ __launch_bounds__(256) void gemm1_kernel(
    const float* __restrict__ emb, const float* __restrict__ W1,
    float* __restrict__ out_emb) {
    __shared__ float As[TK][TM + 4];  // A transposed: As[k][row], padded
    __shared__ float Bs[TK][TN];

    int row0 = blockIdx.x * TM;
    int n0   = blockIdx.y * TN;
    int b    = row0 / U_;           // 128 | 512 -> whole tile is one batch
    int tid  = threadIdx.x;
    int tx   = tid % 16;            // col group
    int ty   = tid / 16;            // row group

    float acc[8][8];
#pragma unroll
    for (int i = 0; i < 8; i++)
#pragma unroll
        for (int j = 0; j < 8; j++) acc[i][j] = 0.f;

    for (int k0 = 0; k0 < UNIT_; k0 += TK) {
        // load A tile: 128 rows x 16 k  (512 float4 slots, 2 per thread)
#pragma unroll
        for (int i = 0; i < 2; i++) {
            int s   = tid + i * 256;
            int r   = s >> 2;           // 0..127
            int kk4 = (s & 3) * 4;      // 0,4,8,12
            float4 v = *(const float4*)(emb + (size_t)(row0 + r) * UNIT_ + k0 + kk4);
            As[kk4 + 0][r] = v.x;
            As[kk4 + 1][r] = v.y;
            As[kk4 + 2][r] = v.z;
            As[kk4 + 3][r] = v.w;
        }
        // load B tile: 16 k x 128 n
#pragma unroll
        for (int i = 0; i < 2; i++) {
            int s  = tid + i * 256;
            int kk = s >> 5;            // 0..15
            int n4 = (s & 31) * 4;
            *(float4*)(&Bs[kk][n4]) =
                *(const float4*)(W1 + (size_t)(k0 + kk) * HID_ + n0 + n4);
        }
        __syncthreads();

#pragma unroll
        for (int kk = 0; kk < TK; kk++) {
            float a[8], bb[8];
            *(float4*)(a)      = *(const float4*)(&As[kk][ty * 8]);
            *(float4*)(a + 4)  = *(const float4*)(&As[kk][ty * 8 + 4]);
            *(float4*)(bb)     = *(const float4*)(&Bs[kk][tx * 8]);
            *(float4*)(bb + 4) = *(const float4*)(&Bs[kk][tx * 8 + 4]);
#pragma unroll
            for (int i = 0; i < 8; i++)
#pragma unroll
                for (int j = 0; j < 8; j++) acc[i][j] += a[i] * bb[j];
        }
        __syncthreads();
    }

    // epilogue: + core_part, relu, store
    float cpv[8];
    const float* cp = g_core_part + b * HID_ + n0 + tx * 8;
    *(float4*)(cpv)     = *(const float4*)(cp);
    *(float4*)(cpv + 4) = *(const float4*)(cp + 4);

#pragma unroll
    for (int i = 0; i < 8; i++) {
        int row = row0 + ty * 8 + i;
        float* o = out_emb + (size_t)row * HID_ + n0 + tx * 8;
        float4 v0, v1;
        v0.x = fmaxf(acc[i][0] + cpv[0], 0.f);
        v0.y = fmaxf(acc[i][1] + cpv[1], 0.f);
        v0.z = fmaxf(acc[i][2] + cpv[2], 0.f);
        v0.w = fmaxf(acc[i][3] + cpv[3], 0.f);
        v1.x = fmaxf(acc[i][4] + cpv[4], 0.f);
        v1.y = fmaxf(acc[i][5] + cpv[5], 0.f);
        v1.z = fmaxf(acc[i][6] + cpv[6], 0.f);
        v1.w = fmaxf(acc[i][7] + cpv[7], 0.f);
        *(float4*)(o)     = v0;
        *(float4*)(o + 4) = v1;
    }
}

// ---------------------------------------------------------------------------
// Kernel 3: logits = hidden @ W2 + b2 -> softmax -> range mask -> probs
// 256 threads = 8 warps; each warp handles 4 rows; grid = M/32 = 1024 blocks.
// W2 transposed in smem: W2t[a][k] for conflict-free float4 reads.
// ---------------------------------------------------------------------------
__global__ __launch_bounds__(256) void head_kernel(
    const float* __restrict__ hidden, const float* __restrict__ W2,
    const float* __restrict__ b2, const int* __restrict__ nr_units,
    const int* __restrict__ nr_own_flags, float* __restrict__ probs) {
    __shared__ float W2t[ACT_ * HID_];   // 48KB exactly

    for (int idx = threadIdx.x; idx < HID_ * ACT_; idx += blockDim.x) {
        int k = idx / ACT_;
        int a = idx % ACT_;
        W2t[a * HID_ + k] = W2[idx];
    }
    __syncthreads();

    int lane = threadIdx.x & 31;
    int warp = threadIdx.x >> 5;
    int rowb = blockIdx.x * 32 + warp * 4;

    float acc[48];
#pragma unroll
    for (int i = 0; i < 48; i++) acc[i] = 0.f;

#pragma unroll
    for (int j = 0; j < 8; j++) {
        int k = j * 128 + lane * 4;
        float4 wv[ACT_];
#pragma unroll
        for (int a = 0; a < ACT_; a++) wv[a] = *(const float4*)(&W2t[a * HID_ + k]);
#pragma unroll
        for (int rr = 0; rr < 4; rr++) {
            float4 h = *(const float4*)(hidden + (size_t)(rowb + rr) * HID_ + k);
#pragma unroll
            for (int a = 0; a < ACT_; a++) {
                float s = acc[rr * ACT_ + a];
                s = fmaf(h.x, wv[a].x, s);
                s = fmaf(h.y, wv[a].y, s);
                s = fmaf(h.z, wv[a].z, s);
                s = fmaf(h.w, wv[a].w, s);
                acc[rr * ACT_ + a] = s;
            }
        }
    }

    // warp reduce all 48 partials
#pragma unroll
    for (int i = 0; i < 48; i++) {
#pragma unroll
        for (int off = 16; off; off >>= 1)
            acc[i] += __shfl_xor_sync(0xffffffffu, acc[i], off);
    }

    if (lane < 4) {
        int row = rowb + lane;
        int b = row / U_;
        int u = row % U_;
        float v[ACT_];
        float m = -3.402823e38f;
#pragma unroll
        for (int a = 0; a < ACT_; a++) {
            v[a] = acc[lane * ACT_ + a] + b2[a];
            m = fmaxf(m, v[a]);
        }
        float s = 0.f;
#pragma unroll
        for (int a = 0; a < ACT_; a++) {
            v[a] = expf(v[a] - m);
            s += v[a];
        }
        bool valid = (u >= nr_own_flags[b]) && (u < nr_units[b]);
        float f = (valid ? 1.0f : 1e-9f) / s;
#pragma unroll
        for (int a = 0; a < ACT_; a++) probs[(size_t)row * ACT_ + a] = v[a] * f;
    }
}

// ---------------------------------------------------------------------------
extern "C" void kernel_launch(void* const* d_in, const int* in_sizes, int n_in,
                              void* d_out, int out_size) {
    const float* core  = (const float*)d_in[0];   // [64,1,512]
    const float* emb   = (const float*)d_in[1];   // [64,512,256]
    const int*   nru   = (const int*)d_in[2];     // [64,1]
    const int*   nrf   = (const int*)d_in[3];     // [64,1]
    const float* W1    = (const float*)d_in[4];   // [768,1024]
    const float* b1    = (const float*)d_in[5];   // [1024]
    const float* W2    = (const float*)d_in[6];   // [1024,12]
    const float* b2    = (const float*)d_in[7];   // [12]

    float* probs   = (float*)d_out;                          // [64,512,12]
    float* out_emb = (float*)d_out + (size_t)M_ * ACT_;      // [64,512,1024]

    // 1) core_part[b][h] = core[b] @ W1[256:768] + b1
    {
        dim3 grid(HID_ / 128, B_);
        core_part_kernel<<<grid, 128>>>(core, W1, b1);
    }
    // 2) hidden = relu(emb @ W1[0:256] + core_part)  (written to output)
    {
        dim3 grid(M_ / TM, HID_ / TN);
        gemm1_kernel<<<grid, 256>>>(emb, W1, out_emb);
    }
    // 3) probs = mask * softmax(hidden @ W2 + b2)
    {
        head_kernel<<<M_ / 32, 256>>>(out_emb, W2, b2, nru, nrf, probs);
    }
}

// round 9
// speedup vs baseline: 2.5300x; 2.5300x over previous
#include <cuda_runtime.h>
#include <math.h>
#include <stdint.h>

#define B_    64
#define U_    512
#define CORE_ 512
#define UNIT_ 256
#define HID_  1024
#define ACT_  12
#define M_    (B_*U_)

// -------------------- scratch (device globals; no allocs) -------------------
__device__ float g_core_part[B_ * HID_];   // core@W1[256:768]+b1  [64,1024]
__device__ float g_W1t[HID_ * UNIT_];      // W1[0:256,:]^T, tf32-rounded [1024,256]

// -------------------- PTX helpers (all plain-sm_103-safe) -------------------
__device__ __forceinline__ uint32_t smem_u32(const void* p) {
    uint32_t a;
    asm("{ .reg .u64 t; cvta.to.shared.u64 t, %1; cvt.u32.u64 %0, t; }" : "=r"(a) : "l"(p));
    return a;
}
#define CP_ASYNC16(dst, src) \
    asm volatile("cp.async.ca.shared.global [%0], [%1], 16;" :: "r"(dst), "l"(src))
#define CP_COMMIT()  asm volatile("cp.async.commit_group;" ::: "memory")
#define CP_WAIT1()   asm volatile("cp.async.wait_group 1;" ::: "memory")
#define CP_WAIT0()   asm volatile("cp.async.wait_group 0;" ::: "memory")

__device__ __forceinline__ void ldsm_x4(uint32_t& r0, uint32_t& r1, uint32_t& r2,
                                        uint32_t& r3, uint32_t addr) {
    asm volatile("ldmatrix.sync.aligned.m8n8.x4.shared.b16 {%0,%1,%2,%3}, [%4];"
                 : "=r"(r0), "=r"(r1), "=r"(r2), "=r"(r3) : "r"(addr));
}
__device__ __forceinline__ void mma_tf32(float* c, const uint32_t* a,
                                         uint32_t b0, uint32_t b1) {
    asm volatile("mma.sync.aligned.m16n8k8.row.col.f32.tf32.tf32.f32 "
                 "{%0,%1,%2,%3},{%4,%5,%6,%7},{%8,%9},{%0,%1,%2,%3};"
                 : "+f"(c[0]), "+f"(c[1]), "+f"(c[2]), "+f"(c[3])
                 : "r"(a[0]), "r"(a[1]), "r"(a[2]), "r"(a[3]), "r"(b0), "r"(b1));
}
__device__ __forceinline__ uint32_t f2tf32(uint32_t x) {
    uint32_t r;
    asm("cvt.rna.tf32.f32 %0, %1;" : "=r"(r) : "f"(__uint_as_float(x)));
    return r;
}

// ---------------------------------------------------------------------------
// Kernel A: transpose W1[0:256,:] -> g_W1t[n][k], tf32-rounded.
// ---------------------------------------------------------------------------
__global__ __launch_bounds__(256) void transpose_kernel(const float* __restrict__ W1) {
    __shared__ float t[32][33];
    int k0 = blockIdx.x * 32, n0 = blockIdx.y * 32;
    int tx = threadIdx.x & 31, ty = threadIdx.x >> 5;
#pragma unroll
    for (int j = ty; j < 32; j += 8)
        t[j][tx] = W1[(size_t)(k0 + j) * HID_ + n0 + tx];
    __syncthreads();
#pragma unroll
    for (int j = ty; j < 32; j += 8) {
        uint32_t r = f2tf32(__float_as_uint(t[tx][j]));
        g_W1t[(size_t)(n0 + j) * UNIT_ + k0 + tx] = __uint_as_float(r);
    }
}

// ---------------------------------------------------------------------------
// Kernel B: core_part[b][h] = core[b] @ W1[256:768][h] + b1[h]   (fp32 exact)
// ---------------------------------------------------------------------------
__global__ __launch_bounds__(512) void core_part_kernel(
    const float* __restrict__ core, const float* __restrict__ W1,
    const float* __restrict__ b1) {
    __shared__ float red[512];
    int b  = blockIdx.y;
    int h  = blockIdx.x * 128 + (threadIdx.x & 127);
    int kg = threadIdx.x >> 7;
    const float* c = core + b * CORE_ + kg * 128;
    const float* w = W1 + (size_t)(UNIT_ + kg * 128) * HID_ + h;
    float acc = 0.f;
#pragma unroll 16
    for (int k = 0; k < 128; k++)
        acc = fmaf(__ldg(c + k), w[(size_t)k * HID_], acc);
    red[threadIdx.x] = acc;
    __syncthreads();
    if (threadIdx.x < 128) {
        g_core_part[b * HID_ + h] = red[threadIdx.x] + red[threadIdx.x + 128] +
                                    red[threadIdx.x + 256] + red[threadIdx.x + 384] + b1[h];
    }
}

// ---------------------------------------------------------------------------
// Kernel C: hidden = relu(emb @ W1t^T + core_part)  via mma.sync tf32
// Block 128x128, K-chunks of 32 (double-buffered cp.async), 8 warps (4M x 2N),
// warp tile 32x64. Smem rows = 8 x 16B chunks, chunk ^= (row&7) swizzle.
// ---------------------------------------------------------------------------
#define STG_A   16384                     // 128 rows * 128 B
#define STG_B   16384
#define SM_A0   0
#define SM_B0   32768
#define SM_CPS  65536                     // 128 floats
#define SM_TOT  (65536 + 512)

__global__ __launch_bounds__(256, 2) void gemm1_kernel(
    const float* __restrict__ emb, float* __restrict__ out_emb) {
    extern __shared__ char smem[];
    uint32_t sbase = smem_u32(smem);
    float* cps = (float*)(smem + SM_CPS);

    int tid  = threadIdx.x;
    int lane = tid & 31, wid = tid >> 5;
    int wm   = wid & 3;          // 0..3  (M)
    int wn   = wid >> 2;         // 0..1  (N)
    int m0   = blockIdx.x * 128;
    int n0   = blockIdx.y * 128;
    int b    = blockIdx.x >> 2;  // 128 rows per block, 512 per batch

    // stage core_part slice for this N tile
    if (tid < 128) cps[tid] = g_core_part[b * HID_ + n0 + tid];

    // cp.async source/dst precompute: thread covers elements e = tid + i*256
    // row = e>>3 (0..127), chunk = e&7; dst chunk swizzled by row&7
    const float* srcA = emb + (size_t)m0 * UNIT_;
    const float* srcB = g_W1t + (size_t)n0 * UNIT_;

    // ldmatrix per-lane address components
    int rowA  = wm * 32 + (lane & 15);            // + mf*16
    int chA   = lane >> 4;                        // + kstep*2
    int rowB  = wn * 64 + ((lane >> 4) << 3) + (lane & 7);   // + nfp*16
    int chB   = (lane >> 3) & 1;                  // + kstep*2

    float c[2][8][4];
#pragma unroll
    for (int mf = 0; mf < 2; mf++)
#pragma unroll
        for (int nf = 0; nf < 8; nf++)
#pragma unroll
            for (int j = 0; j < 4; j++) c[mf][nf][j] = 0.f;

    // ---- issue stage for K-chunk kc into buffer s ----
    auto issue = [&](int kc, int s) {
#pragma unroll
        for (int i = 0; i < 4; i++) {
            int e = tid + i * 256;
            int r = e >> 3, ch = e & 7;
            uint32_t dst = sbase + SM_A0 + s * STG_A + r * 128 + (((uint32_t)(ch ^ (r & 7))) << 4);
            CP_ASYNC16(dst, srcA + (size_t)r * UNIT_ + kc * 32 + ch * 4);
        }
#pragma unroll
        for (int i = 0; i < 4; i++) {
            int e = tid + i * 256;
            int r = e >> 3, ch = e & 7;
            uint32_t dst = sbase + SM_B0 + s * STG_B + r * 128 + (((uint32_t)(ch ^ (r & 7))) << 4);
            CP_ASYNC16(dst, srcB + (size_t)r * UNIT_ + kc * 32 + ch * 4);
        }
        CP_COMMIT();
    };

    issue(0, 0);

#pragma unroll 1
    for (int kc = 0; kc < UNIT_ / 32; kc++) {
        int s = kc & 1;
        if (kc + 1 < UNIT_ / 32) { issue(kc + 1, s ^ 1); CP_WAIT1(); }
        else                     { CP_WAIT0(); }
        __syncthreads();

        uint32_t abase = sbase + SM_A0 + s * STG_A;
        uint32_t bbase = sbase + SM_B0 + s * STG_B;
#pragma unroll
        for (int ks = 0; ks < 4; ks++) {
            uint32_t a[2][4];
#pragma unroll
            for (int mf = 0; mf < 2; mf++) {
                int r = rowA + mf * 16;
                int ch = ks * 2 + chA;
                uint32_t addr = abase + r * 128 + (((uint32_t)(ch ^ (r & 7))) << 4);
                ldsm_x4(a[mf][0], a[mf][1], a[mf][2], a[mf][3], addr);
#pragma unroll
                for (int j = 0; j < 4; j++) a[mf][j] = f2tf32(a[mf][j]);
            }
#pragma unroll
            for (int nfp = 0; nfp < 4; nfp++) {
                int r = rowB + nfp * 16;
                int ch = ks * 2 + chB;
                uint32_t addr = bbase + r * 128 + (((uint32_t)(ch ^ (r & 7))) << 4);
                uint32_t b0, b1, b2, b3;
                ldsm_x4(b0, b1, b2, b3, addr);
#pragma unroll
                for (int mf = 0; mf < 2; mf++) {
                    mma_tf32(c[mf][nfp * 2 + 0], a[mf], b0, b1);
                    mma_tf32(c[mf][nfp * 2 + 1], a[mf], b2, b3);
                }
            }
        }
        __syncthreads();
    }

    // ---- epilogue: + core_part, relu, direct float2 stores ----
    int g   = lane >> 2;         // 0..7
    int tig = lane & 3;          // 0..3
#pragma unroll
    for (int mf = 0; mf < 2; mf++) {
        int r0g = m0 + wm * 32 + mf * 16 + g;
#pragma unroll
        for (int nf = 0; nf < 8; nf++) {
            int colL = wn * 64 + nf * 8 + tig * 2;
            float cp0 = cps[colL], cp1 = cps[colL + 1];
            float2 v0, v1;
            v0.x = fmaxf(c[mf][nf][0] + cp0, 0.f);
            v0.y = fmaxf(c[mf][nf][1] + cp1, 0.f);
            v1.x = fmaxf(c[mf][nf][2] + cp0, 0.f);
            v1.y = fmaxf(c[mf][nf][3] + cp1, 0.f);
            *(float2*)(out_emb + (size_t)r0g * HID_ + n0 + colL)       = v0;
            *(float2*)(out_emb + (size_t)(r0g + 8) * HID_ + n0 + colL) = v1;
        }
    }
}

// ---------------------------------------------------------------------------
// Kernel D: logits = hidden @ W2 + b2 -> softmax -> range mask
// ---------------------------------------------------------------------------
__global__ __launch_bounds__(256) void head_kernel(
    const float* __restrict__ hidden, const float* __restrict__ W2,
    const float* __restrict__ b2, const int* __restrict__ nr_units,
    const int* __restrict__ nr_own_flags, float* __restrict__ probs) {
    __shared__ float W2t[ACT_ * HID_];
    for (int idx = threadIdx.x; idx < HID_ * ACT_; idx += blockDim.x) {
        int k = idx / ACT_, a = idx % ACT_;
        W2t[a * HID_ + k] = W2[idx];
    }
    __syncthreads();

    int lane = threadIdx.x & 31, warp = threadIdx.x >> 5;
    int rowb = blockIdx.x * 32 + warp * 4;

    float acc[48];
#pragma unroll
    for (int i = 0; i < 48; i++) acc[i] = 0.f;

#pragma unroll
    for (int j = 0; j < 8; j++) {
        int k = j * 128 + lane * 4;
        float4 wv[ACT_];
#pragma unroll
        for (int a = 0; a < ACT_; a++) wv[a] = *(const float4*)(&W2t[a * HID_ + k]);
#pragma unroll
        for (int rr = 0; rr < 4; rr++) {
            float4 h = *(const float4*)(hidden + (size_t)(rowb + rr) * HID_ + k);
#pragma unroll
            for (int a = 0; a < ACT_; a++) {
                float s = acc[rr * ACT_ + a];
                s = fmaf(h.x, wv[a].x, s);
                s = fmaf(h.y, wv[a].y, s);
                s = fmaf(h.z, wv[a].z, s);
                s = fmaf(h.w, wv[a].w, s);
                acc[rr * ACT_ + a] = s;
            }
        }
    }
#pragma unroll
    for (int i = 0; i < 48; i++) {
#pragma unroll
        for (int off = 16; off; off >>= 1)
            acc[i] += __shfl_xor_sync(0xffffffffu, acc[i], off);
    }
    if (lane < 4) {
        int row = rowb + lane;
        int b = row / U_, u = row % U_;
        float v[ACT_], m = -3.402823e38f;
#pragma unroll
        for (int a = 0; a < ACT_; a++) {
            v[a] = acc[lane * ACT_ + a] + b2[a];
            m = fmaxf(m, v[a]);
        }
        float s = 0.f;
#pragma unroll
        for (int a = 0; a < ACT_; a++) { v[a] = expf(v[a] - m); s += v[a]; }
        bool valid = (u >= nr_own_flags[b]) && (u < nr_units[b]);
        float f = (valid ? 1.0f : 1e-9f) / s;
#pragma unroll
        for (int a = 0; a < ACT_; a++) probs[(size_t)row * ACT_ + a] = v[a] * f;
    }
}

// ---------------------------------------------------------------------------
extern "C" void kernel_launch(void* const* d_in, const int* in_sizes, int n_in,
                              void* d_out, int out_size) {
    const float* core = (const float*)d_in[0];
    const float* emb  = (const float*)d_in[1];
    const int*   nru  = (const int*)d_in[2];
    const int*   nrf  = (const int*)d_in[3];
    const float* W1   = (const float*)d_in[4];
    const float* b1   = (const float*)d_in[5];
    const float* W2   = (const float*)d_in[6];
    const float* b2   = (const float*)d_in[7];

    float* probs   = (float*)d_out;
    float* out_emb = (float*)d_out + (size_t)M_ * ACT_;

    cudaFuncSetAttribute(gemm1_kernel, cudaFuncAttributeMaxDynamicSharedMemorySize, SM_TOT);

    { dim3 g(UNIT_ / 32, HID_ / 32); transpose_kernel<<<g, 256>>>(W1); }
    { dim3 g(HID_ / 128, B_); core_part_kernel<<<g, 512>>>(core, W1, b1); }
    { dim3 g(M_ / 128, HID_ / 128); gemm1_kernel<<<g, 256, SM_TOT>>>(emb, out_emb); }
    head_kernel<<<M_ / 32, 256>>>(out_emb, W2, b2, nru, nrf, probs);
}